// round 2
// baseline (speedup 1.0000x reference)
#include <cuda_runtime.h>
#include <cuda_bf16.h>

typedef unsigned long long ull;

#define KD 64      // feature dimension
#define LD 8192    // leading dim of transposed feature matrix
#define MB 32      // goals per block
#define NB 128     // features per tile
#define NSPLIT 2   // feature-dim split per step

// ---------------- scratch (__device__ globals; no allocation) ----------------
__device__ float g_FT[KD * LD];          // transposed features [64][8192]
__device__ float g_norms[LD];            // |f|^2
__device__ unsigned g_candU[4096 * NSPLIT * 3];
__device__ int      g_candI[4096 * NSPLIT * 3];
__device__ ull g_skeys[LD];              // sort keys for permutation
__device__ int g_px[LD];                 // intermediate permutation
__device__ int g_perm[LD];               // final permutation (rand_inds = first 4096)

// ---------------- threefry2x32 (exact JAX) ----------------
__device__ __forceinline__ void tf2x32(unsigned k0, unsigned k1,
                                       unsigned c0, unsigned c1,
                                       unsigned &o0, unsigned &o1) {
    unsigned ks2 = k0 ^ k1 ^ 0x1BD11BDAu;
    unsigned x0 = c0 + k0, x1 = c1 + k1;
#define TF_RND(r) { x0 += x1; x1 = (x1 << (r)) | (x1 >> (32 - (r))); x1 ^= x0; }
    TF_RND(13) TF_RND(15) TF_RND(26) TF_RND(6)   x0 += k1;  x1 += ks2 + 1u;
    TF_RND(17) TF_RND(29) TF_RND(16) TF_RND(24)  x0 += ks2; x1 += k0 + 2u;
    TF_RND(13) TF_RND(15) TF_RND(26) TF_RND(6)   x0 += k0;  x1 += k1 + 3u;
    TF_RND(17) TF_RND(29) TF_RND(16) TF_RND(24)  x0 += k1;  x1 += ks2 + 4u;
    TF_RND(13) TF_RND(15) TF_RND(26) TF_RND(6)   x0 += ks2; x1 += k0 + 5u;
#undef TF_RND
    o0 = x0; o1 = x1;
}

// jax.random.permutation(key(42), 8192) under jax_threefry_partitionable=True:
// 2 rounds of:
//   key, subkey = split(key)  -> counters (0,0) and (0,1); keys[i] = (y0, y1)
//   bits = random_bits(subkey, 32, (8192,)) -> counter (0, i); bits[i] = y0 ^ y1
//   stable ascending sort_key_val(bits, x)
// Stability via packed u64 key = (bits<<32) | position.
__global__ void perm_kernel() {
    int tid = threadIdx.x;
    unsigned key0 = 0u, key1 = 42u;   // threefry_seed(42) = [42>>32, 42&mask]
    for (int round = 0; round < 2; round++) {
        unsigned n0, n1, s0, s1;
        tf2x32(key0, key1, 0u, 0u, n0, n1);   // keys[0] = new key
        tf2x32(key0, key1, 0u, 1u, s0, s1);   // keys[1] = subkey
        key0 = n0; key1 = n1;
        // random_bits(subkey, 32, (8192,)): counter (0, i), fold y0 ^ y1
        for (int j = tid; j < LD; j += blockDim.x) {
            unsigned lo, hi;
            tf2x32(s0, s1, 0u, (unsigned)j, lo, hi);
            g_skeys[j] = ((ull)(lo ^ hi) << 32) | (unsigned)j;
        }
        __syncthreads();
        // bitonic sort ascending, 8192 u64
        for (int size = 2; size <= LD; size <<= 1) {
            for (int stride = size >> 1; stride > 0; stride >>= 1) {
                for (int t = tid; t < LD / 2; t += blockDim.x) {
                    int i = ((t & ~(stride - 1)) << 1) | (t & (stride - 1));
                    int j2 = i + stride;
                    bool up = (i & size) == 0;
                    ull ki = g_skeys[i], kj = g_skeys[j2];
                    if ((ki > kj) == up) { g_skeys[i] = kj; g_skeys[j2] = ki; }
                }
                __syncthreads();
            }
        }
        // gather carried values: x_new[j] = x_old[pos]; round 0: x_old = arange
        for (int j = tid; j < LD; j += blockDim.x) {
            int pos = (int)(g_skeys[j] & 0xffffffffu);
            if (round == 0) g_px[j]   = pos;
            else            g_perm[j] = g_px[pos];
        }
        __syncthreads();
    }
}

// ---------------- transpose rows[n][64] -> g_FT[64][8192] ----------------
__global__ void transpose_k(const float* __restrict__ in, int n) {
    __shared__ float t[32][33];
    int f0 = blockIdx.x * 32, d0 = blockIdx.y * 32;
    int tx = threadIdx.x, ty = threadIdx.y;
    t[ty][tx] = in[(size_t)(f0 + ty) * KD + d0 + tx];
    __syncthreads();
    g_FT[(size_t)(d0 + ty) * LD + f0 + tx] = t[tx][ty];
}

// ---------------- norms: |f|^2 ----------------
__global__ void norms_k(int n) {
    int f = blockIdx.x * blockDim.x + threadIdx.x;
    if (f >= n) return;
    float s = 0.f;
#pragma unroll
    for (int k = 0; k < KD; k++) {
        float v = g_FT[(size_t)k * LD + f];
        float p = __fmul_rn(v, v);
        s = __fadd_rn(s, p);
    }
    g_norms[f] = s;
}

// ---------------- ordered-float key for tie-break-by-lower-index min ----------------
__device__ __forceinline__ unsigned fkey(float f) {
    unsigned u = __float_as_uint(f);
    return (u & 0x80000000u) ? ~u : (u | 0x80000000u);
}

// ---------------- KNN top-3: GEMM-tiled distance + in-register top-3 ----------------
// grid = (ngoals/32, NSPLIT), block = 256. Each warp owns 4 goals; each lane owns
// 4 features per tile. d2 = (|g|^2 + |f|^2) - 2*dot, fp32.
__global__ __launch_bounds__(256) void knn_k(int nfeat, int usePerm) {
    __shared__ float Gs[KD][MB];   // goal tile (transposed)
    __shared__ float Fs[KD][NB];   // feature tile (transposed)
    __shared__ float Ns[NB];       // feature norms
    __shared__ float Gn[MB];       // goal norms

    int tid = threadIdx.x;
    int lane = tid & 31, w = tid >> 5;
    int g0 = blockIdx.x * MB;
    int half = nfeat / NSPLIT;
    int fBeg = blockIdx.y * half, fEnd = fBeg + half;

    for (int i = tid; i < KD * MB; i += 256) {
        int k = i >> 5, j = i & 31;
        int src = usePerm ? g_perm[g0 + j] : (g0 + j);
        Gs[k][j] = g_FT[(size_t)k * LD + src];
    }
    if (tid < MB) {
        int src = usePerm ? g_perm[g0 + tid] : (g0 + tid);
        Gn[tid] = g_norms[src];
    }

    float bv[4][3]; int bi[4][3];
#pragma unroll
    for (int r = 0; r < 4; r++)
#pragma unroll
        for (int t = 0; t < 3; t++) { bv[r][t] = 3.402823466e38f; bi[r][t] = 0; }

    for (int f0 = fBeg; f0 < fEnd; f0 += NB) {
        __syncthreads();
        for (int i = tid; i < KD * NB / 4; i += 256) {
            int k = i >> 5, c = i & 31;
            reinterpret_cast<float4*>(&Fs[k][0])[c] =
                reinterpret_cast<const float4*>(&g_FT[(size_t)k * LD + f0])[c];
        }
        if (tid < NB) Ns[tid] = g_norms[f0 + tid];
        __syncthreads();

        float acc[4][4];
#pragma unroll
        for (int r = 0; r < 4; r++)
#pragma unroll
            for (int c = 0; c < 4; c++) acc[r][c] = 0.f;

#pragma unroll
        for (int k = 0; k < KD; k++) {
            float4 fv = *reinterpret_cast<const float4*>(&Fs[k][lane * 4]);
            float4 gv = *reinterpret_cast<const float4*>(&Gs[k][w * 4]);
            acc[0][0] += gv.x * fv.x; acc[0][1] += gv.x * fv.y; acc[0][2] += gv.x * fv.z; acc[0][3] += gv.x * fv.w;
            acc[1][0] += gv.y * fv.x; acc[1][1] += gv.y * fv.y; acc[1][2] += gv.y * fv.z; acc[1][3] += gv.y * fv.w;
            acc[2][0] += gv.z * fv.x; acc[2][1] += gv.z * fv.y; acc[2][2] += gv.z * fv.z; acc[2][3] += gv.z * fv.w;
            acc[3][0] += gv.w * fv.x; acc[3][1] += gv.w * fv.y; acc[3][2] += gv.w * fv.z; acc[3][3] += gv.w * fv.w;
        }

        float4 nf4 = *reinterpret_cast<const float4*>(&Ns[lane * 4]);
        float nfa[4] = {nf4.x, nf4.y, nf4.z, nf4.w};
#pragma unroll
        for (int r = 0; r < 4; r++) {
            float gn = Gn[w * 4 + r];
#pragma unroll
            for (int c = 0; c < 4; c++) {
                float v = (gn + nfa[c]) - 2.0f * acc[r][c];
                int idx = f0 + lane * 4 + c;
                if (v < bv[r][2]) {
                    if (v < bv[r][1]) {
                        bv[r][2] = bv[r][1]; bi[r][2] = bi[r][1];
                        if (v < bv[r][0]) {
                            bv[r][1] = bv[r][0]; bi[r][1] = bi[r][0];
                            bv[r][0] = v; bi[r][0] = idx;
                        } else { bv[r][1] = v; bi[r][1] = idx; }
                    } else { bv[r][2] = v; bi[r][2] = idx; }
                }
            }
        }
    }

    // per-goal warp merge: 3 rounds of u64 min + pop (keys unique: idx unique)
#pragma unroll
    for (int r = 0; r < 4; r++) {
        ull cand[3];
#pragma unroll
        for (int t = 0; t < 3; t++)
            cand[t] = ((ull)fkey(bv[r][t]) << 32) | (unsigned)bi[r][t];
        int p = 0;
#pragma unroll
        for (int t = 0; t < 3; t++) {
            ull cur = (p < 3) ? cand[p] : ~0ull;
            ull m = cur;
            for (int off = 16; off; off >>= 1) {
                ull o = __shfl_xor_sync(0xffffffffu, m, off);
                if (o < m) m = o;
            }
            if (cur == m) p++;
            if (lane == 0) {
                int g = g0 + w * 4 + r;
                int base = (g * NSPLIT + blockIdx.y) * 3 + t;
                g_candU[base] = (unsigned)(m >> 32);
                g_candI[base] = (int)(m & 0xffffffffu);
            }
        }
    }
}

// ---------------- merge split candidates + gather mean ----------------
__global__ void finalize_k(const float* __restrict__ Frow, int ngoals,
                           float* __restrict__ outp) {
    int w = threadIdx.x >> 5, lane = threadIdx.x & 31;
    int g = blockIdx.x * 8 + w;
    if (g >= ngoals) return;
    ull key = ~0ull;
    if (lane < NSPLIT * 3)
        key = ((ull)g_candU[g * NSPLIT * 3 + lane] << 32) |
              (unsigned)g_candI[g * NSPLIT * 3 + lane];
    int idxs[3];
#pragma unroll
    for (int t = 0; t < 3; t++) {
        ull m = key;
        for (int off = 16; off; off >>= 1) {
            ull o = __shfl_xor_sync(0xffffffffu, m, off);
            if (o < m) m = o;
        }
        if (key == m) key = ~0ull;
        idxs[t] = (int)(m & 0xffffffffu);
    }
    const float* r0 = Frow + (size_t)idxs[0] * KD;
    const float* r1 = Frow + (size_t)idxs[1] * KD;
    const float* r2 = Frow + (size_t)idxs[2] * KD;
#pragma unroll
    for (int d = lane; d < KD; d += 32)
        outp[(size_t)g * KD + d] = ((r0[d] + r1[d]) + r2[d]) / 3.0f;
}

// ---------------- orchestration ----------------
extern "C" void kernel_launch(void* const* d_in, const int* in_sizes, int n_in,
                              void* d_out, int out_size) {
    const float* x = (const float*)d_in[0];   // [4096, 64] fp32
    float* out = (float*)d_out;               // [12288, 64] fp32

    // permutation (independent of data; needed only for step 2)
    perm_kernel<<<1, 1024>>>();

    // rows [0, 4096) = x
    cudaMemcpyAsync(out, x, (size_t)4096 * KD * sizeof(float),
                    cudaMemcpyDeviceToDevice);

    // ---- step 1: feats = goals = x (4096) ----
    transpose_k<<<dim3(4096 / 32, 2), dim3(32, 32)>>>(x, 4096);
    norms_k<<<4096 / 256, 256>>>(4096);
    knn_k<<<dim3(4096 / MB, NSPLIT), 256>>>(4096, 0);
    finalize_k<<<4096 / 8, 256>>>(x, 4096, out + (size_t)4096 * KD);

    // ---- step 2: feats = out[0:8192], goals = feats[perm[:4096]] ----
    transpose_k<<<dim3(8192 / 32, 2), dim3(32, 32)>>>(out, 8192);
    norms_k<<<8192 / 256, 256>>>(8192);
    knn_k<<<dim3(4096 / MB, NSPLIT), 256>>>(8192, 1);
    finalize_k<<<4096 / 8, 256>>>(out, 4096, out + (size_t)8192 * KD);
}

// round 3
// speedup vs baseline: 1.5010x; 1.5010x over previous
#include <cuda_runtime.h>
#include <cuda_bf16.h>

typedef unsigned long long ull;

#define KD 64      // feature dimension
#define LD 8192    // leading dim of transposed feature matrix
#define MB 32      // goals per block
#define NB 256     // features per tile
#define NSPLIT 2   // feature-dim split per step
#define NPTS 8192

// ---------------- scratch (__device__ globals; no allocation) ----------------
__device__ float g_FT[KD * LD];          // transposed features [64][8192]
__device__ float g_norms[LD];            // |f|^2
__device__ unsigned g_candU[4096 * NSPLIT * 3];
__device__ int      g_candI[4096 * NSPLIT * 3];
__device__ ull g_kA[NPTS], g_kB[NPTS];   // round-1/2 sort keys (bits<<32|pos)
__device__ int g_rA[NPTS], g_rB[NPTS];   // ranks
__device__ int g_perm[NPTS];             // final permutation (rand_inds = first 4096)

// ---------------- threefry2x32 (exact JAX) ----------------
__device__ __forceinline__ void tf2x32(unsigned k0, unsigned k1,
                                       unsigned c0, unsigned c1,
                                       unsigned &o0, unsigned &o1) {
    unsigned ks2 = k0 ^ k1 ^ 0x1BD11BDAu;
    unsigned x0 = c0 + k0, x1 = c1 + k1;
#define TF_RND(r) { x0 += x1; x1 = (x1 << (r)) | (x1 >> (32 - (r))); x1 ^= x0; }
    TF_RND(13) TF_RND(15) TF_RND(26) TF_RND(6)   x0 += k1;  x1 += ks2 + 1u;
    TF_RND(17) TF_RND(29) TF_RND(16) TF_RND(24)  x0 += ks2; x1 += k0 + 2u;
    TF_RND(13) TF_RND(15) TF_RND(26) TF_RND(6)   x0 += k0;  x1 += k1 + 3u;
    TF_RND(17) TF_RND(29) TF_RND(16) TF_RND(24)  x0 += k1;  x1 += ks2 + 4u;
    TF_RND(13) TF_RND(15) TF_RND(26) TF_RND(6)   x0 += ks2; x1 += k0 + 5u;
#undef TF_RND
    o0 = x0; o1 = x1;
}

// subkeys for the two permutation rounds (partitionable threefry):
// round r: key,subkey = split(key) with counters (0,0),(0,1); seed key = (0,42)
__device__ __forceinline__ void subkeys(unsigned &s10, unsigned &s11,
                                        unsigned &s20, unsigned &s21) {
    unsigned n0, n1;
    tf2x32(0u, 42u, 0u, 0u, n0, n1);      // new key after round-1 split
    tf2x32(0u, 42u, 0u, 1u, s10, s11);    // round-1 subkey
    tf2x32(n0, n1, 0u, 1u, s20, s21);     // round-2 subkey
}

// bits[i] = y0 ^ y1 with counter (0, i); stable-sort key = (bits<<32) | i
__global__ void keys_k() {
    int i = blockIdx.x * blockDim.x + threadIdx.x;
    if (i >= NPTS) return;
    unsigned s10, s11, s20, s21;
    subkeys(s10, s11, s20, s21);
    unsigned lo, hi;
    tf2x32(s10, s11, 0u, (unsigned)i, lo, hi);
    g_kA[i] = ((ull)(lo ^ hi) << 32) | (unsigned)i;
    tf2x32(s20, s21, 0u, (unsigned)i, lo, hi);
    g_kB[i] = ((ull)(lo ^ hi) << 32) | (unsigned)i;
}

// rank[i] = #{j : key_j < key_i}  (keys unique) -> stable-sort destination slot
__global__ __launch_bounds__(256) void rank_k() {
    __shared__ ull tile[2048];
    const ull* K = blockIdx.y ? g_kB : g_kA;
    int i = blockIdx.x * 256 + threadIdx.x;
    ull my = K[i];
    int cnt = 0;
    for (int t = 0; t < NPTS; t += 2048) {
        for (int j = threadIdx.x; j < 2048; j += 256) tile[j] = K[t + j];
        __syncthreads();
#pragma unroll 8
        for (int j = 0; j < 2048; j++) cnt += (tile[j] < my);
        __syncthreads();
    }
    (blockIdx.y ? g_rB : g_rA)[i] = cnt;
}

// perm[rB[rA[i]]] = i   (x1[rA[i]] = i; x2[rB[j]] = x1[j])
__global__ void compose_k() {
    int i = blockIdx.x * blockDim.x + threadIdx.x;
    if (i >= NPTS) return;
    g_perm[g_rB[g_rA[i]]] = i;
}

// ---------------- transpose rows[n][64] -> g_FT[64][8192] ----------------
__global__ void transpose_k(const float* __restrict__ in, int n) {
    __shared__ float t[32][33];
    int f0 = blockIdx.x * 32, d0 = blockIdx.y * 32;
    int tx = threadIdx.x, ty = threadIdx.y;
    t[ty][tx] = in[(size_t)(f0 + ty) * KD + d0 + tx];
    __syncthreads();
    g_FT[(size_t)(d0 + ty) * LD + f0 + tx] = t[tx][ty];
}

// ---------------- norms: |f|^2 ----------------
__global__ void norms_k(int n) {
    int f = blockIdx.x * blockDim.x + threadIdx.x;
    if (f >= n) return;
    float s = 0.f;
#pragma unroll
    for (int k = 0; k < KD; k++) {
        float v = g_FT[(size_t)k * LD + f];
        s = __fadd_rn(s, __fmul_rn(v, v));
    }
    g_norms[f] = s;
}

// ---------------- ordered-float key for tie-break-by-lower-index min ----------------
__device__ __forceinline__ unsigned fkey(float f) {
    unsigned u = __float_as_uint(f);
    return (u & 0x80000000u) ? ~u : (u | 0x80000000u);
}

__device__ __forceinline__ void fma_x2(ull &acc, ull a, ull b) {
    asm("fma.rn.f32x2 %0, %1, %2, %3;" : "=l"(acc) : "l"(a), "l"(b), "l"(acc));
}

// top-3 insert (value, index)
__device__ __forceinline__ void top3_ins(float v, int idx, float* bv, int* bi) {
    if (v < bv[2]) {
        if (v < bv[1]) {
            bv[2] = bv[1]; bi[2] = bi[1];
            if (v < bv[0]) {
                bv[1] = bv[0]; bi[1] = bi[0];
                bv[0] = v; bi[0] = idx;
            } else { bv[1] = v; bi[1] = idx; }
        } else { bv[2] = v; bi[2] = idx; }
    }
}

// ---------------- KNN top-3: f32x2 GEMM-tiled distance + in-register top-3 ---------
// grid = (4096/MB, NSPLIT), block = 256. Warp w owns goals [w*4, w*4+4);
// lane owns feats {lane*4..+3} and {128+lane*4..+3} of the 256-feat tile.
// Goals duplicated in smem as {g,g} so the f32x2 splat is a free LDS.64 broadcast.
__global__ __launch_bounds__(256, 2) void knn_k(int nfeat, int usePerm) {
    extern __shared__ float sm[];
    float* Fs  = sm;                       // [64][256]
    float* Gs2 = Fs + KD * NB;             // [64][32*2] duplicated goal pairs
    float* Ns  = Gs2 + KD * MB * 2;        // [256]
    float* Gn  = Ns + NB;                  // [32]
    ulonglong2* FsV = (ulonglong2*)Fs;     // row k: 64 entries (float4 each)
    ull* GsU = (ull*)Gs2;                  // row k: 32 entries ({g,g})
    float4* Ns4 = (float4*)Ns;

    int tid = threadIdx.x;
    int lane = tid & 31, w = tid >> 5;
    int g0 = blockIdx.x * MB;
    int half = nfeat / NSPLIT;
    int fBeg = blockIdx.y * half, fEnd = fBeg + half;

    for (int i = tid; i < KD * MB; i += 256) {
        int k = i >> 5, j = i & 31;
        int src = usePerm ? g_perm[g0 + j] : (g0 + j);
        float v = g_FT[(size_t)k * LD + src];
        ((float2*)Gs2)[k * MB + j] = make_float2(v, v);
    }
    if (tid < MB) {
        int src = usePerm ? g_perm[g0 + tid] : (g0 + tid);
        Gn[tid] = g_norms[src];
    }

    float bv[4][3]; int bi[4][3];
#pragma unroll
    for (int r = 0; r < 4; r++)
#pragma unroll
        for (int t = 0; t < 3; t++) { bv[r][t] = 3.402823466e38f; bi[r][t] = 0; }

    for (int f0 = fBeg; f0 < fEnd; f0 += NB) {
        __syncthreads();
        for (int i = tid; i < KD * NB / 4; i += 256) {
            int k = i >> 6, c = i & 63;
            ((float4*)Fs)[k * 64 + c] =
                *reinterpret_cast<const float4*>(&g_FT[(size_t)k * LD + f0 + 4 * c]);
        }
        Ns[tid] = g_norms[f0 + tid];
        __syncthreads();

        ull acc[4][4];
#pragma unroll
        for (int r = 0; r < 4; r++)
#pragma unroll
            for (int p = 0; p < 4; p++) acc[r][p] = 0ull;

#pragma unroll 16
        for (int k = 0; k < KD; k++) {
            ulonglong2 qa = FsV[k * 64 + lane];        // feats lane*4 .. +3
            ulonglong2 qb = FsV[k * 64 + 32 + lane];   // feats 128+lane*4 .. +3
            ull fp[4] = { qa.x, qa.y, qb.x, qb.y };
            ull gA = GsU[k * MB + w * 4 + 0];
            ull gB = GsU[k * MB + w * 4 + 1];
            ull gC = GsU[k * MB + w * 4 + 2];
            ull gD = GsU[k * MB + w * 4 + 3];
#pragma unroll
            for (int p = 0; p < 4; p++) {
                fma_x2(acc[0][p], gA, fp[p]);
                fma_x2(acc[1][p], gB, fp[p]);
                fma_x2(acc[2][p], gC, fp[p]);
                fma_x2(acc[3][p], gD, fp[p]);
            }
        }

        float4 na = Ns4[lane], nb2 = Ns4[32 + lane];
        float nf[8] = { na.x, na.y, na.z, na.w, nb2.x, nb2.y, nb2.z, nb2.w };
        int base1 = f0 + lane * 4, base2 = f0 + 128 + lane * 4;
#pragma unroll
        for (int r = 0; r < 4; r++) {
            float gn = Gn[w * 4 + r];
#pragma unroll
            for (int p = 0; p < 4; p++) {
                float dlo = __uint_as_float((unsigned)(acc[r][p]));
                float dhi = __uint_as_float((unsigned)(acc[r][p] >> 32));
                int c0 = (p < 2) ? (base1 + p * 2) : (base2 + (p - 2) * 2);
                int e0 = (p < 2) ? (p * 2) : (4 + (p - 2) * 2);
                float v0 = fmaf(-2.0f, dlo, gn + nf[e0]);
                float v1 = fmaf(-2.0f, dhi, gn + nf[e0 + 1]);
                top3_ins(v0, c0,     bv[r], bi[r]);
                top3_ins(v1, c0 + 1, bv[r], bi[r]);
            }
        }
    }

    // per-goal warp merge: 3 rounds of u64 min + pop (keys unique: idx unique)
#pragma unroll
    for (int r = 0; r < 4; r++) {
        ull cand[3];
#pragma unroll
        for (int t = 0; t < 3; t++)
            cand[t] = ((ull)fkey(bv[r][t]) << 32) | (unsigned)bi[r][t];
        int p = 0;
#pragma unroll
        for (int t = 0; t < 3; t++) {
            ull cur = (p < 3) ? cand[p] : ~0ull;
            ull m = cur;
            for (int off = 16; off; off >>= 1) {
                ull o = __shfl_xor_sync(0xffffffffu, m, off);
                if (o < m) m = o;
            }
            if (cur == m) p++;
            if (lane == 0) {
                int g = g0 + w * 4 + r;
                int base = (g * NSPLIT + blockIdx.y) * 3 + t;
                g_candU[base] = (unsigned)(m >> 32);
                g_candI[base] = (int)(m & 0xffffffffu);
            }
        }
    }
}

// ---------------- merge split candidates + gather mean ----------------
__global__ void finalize_k(const float* __restrict__ Frow, int ngoals,
                           float* __restrict__ outp) {
    int w = threadIdx.x >> 5, lane = threadIdx.x & 31;
    int g = blockIdx.x * 8 + w;
    if (g >= ngoals) return;
    ull key = ~0ull;
    if (lane < NSPLIT * 3)
        key = ((ull)g_candU[g * NSPLIT * 3 + lane] << 32) |
              (unsigned)g_candI[g * NSPLIT * 3 + lane];
    int idxs[3];
#pragma unroll
    for (int t = 0; t < 3; t++) {
        ull m = key;
        for (int off = 16; off; off >>= 1) {
            ull o = __shfl_xor_sync(0xffffffffu, m, off);
            if (o < m) m = o;
        }
        if (key == m) key = ~0ull;
        idxs[t] = (int)(m & 0xffffffffu);
    }
    const float* r0 = Frow + (size_t)idxs[0] * KD;
    const float* r1 = Frow + (size_t)idxs[1] * KD;
    const float* r2 = Frow + (size_t)idxs[2] * KD;
#pragma unroll
    for (int d = lane; d < KD; d += 32)
        outp[(size_t)g * KD + d] = ((r0[d] + r1[d]) + r2[d]) / 3.0f;
}

// ---------------- orchestration ----------------
extern "C" void kernel_launch(void* const* d_in, const int* in_sizes, int n_in,
                              void* d_out, int out_size) {
    const float* x = (const float*)d_in[0];   // [4096, 64] fp32
    float* out = (float*)d_out;               // [12288, 64] fp32

    const int KNN_SMEM = KD * NB * 4 + KD * MB * 8 + NB * 4 + MB * 4;  // 83072
    cudaFuncSetAttribute(knn_k, cudaFuncAttributeMaxDynamicSharedMemorySize,
                         KNN_SMEM);

    // permutation via rank counting (needed only for step 2)
    keys_k<<<NPTS / 512, 512>>>();
    rank_k<<<dim3(NPTS / 256, 2), 256>>>();
    compose_k<<<NPTS / 512, 512>>>();

    // rows [0, 4096) = x
    cudaMemcpyAsync(out, x, (size_t)4096 * KD * sizeof(float),
                    cudaMemcpyDeviceToDevice);

    // ---- step 1: feats = goals = x (4096) ----
    transpose_k<<<dim3(4096 / 32, 2), dim3(32, 32)>>>(x, 4096);
    norms_k<<<4096 / 256, 256>>>(4096);
    knn_k<<<dim3(4096 / MB, NSPLIT), 256, KNN_SMEM>>>(4096, 0);
    finalize_k<<<4096 / 8, 256>>>(x, 4096, out + (size_t)4096 * KD);

    // ---- step 2: feats = out[0:8192], goals = feats[perm[:4096]] ----
    transpose_k<<<dim3(8192 / 32, 2), dim3(32, 32)>>>(out, 8192);
    norms_k<<<8192 / 256, 256>>>(8192);
    knn_k<<<dim3(4096 / MB, NSPLIT), 256, KNN_SMEM>>>(8192, 1);
    finalize_k<<<4096 / 8, 256>>>(out, 4096, out + (size_t)8192 * KD);
}

// round 4
// speedup vs baseline: 1.7899x; 1.1925x over previous
#include <cuda_runtime.h>
#include <cuda_bf16.h>

typedef unsigned long long ull;

#define KD 64      // feature dimension
#define LD 8192    // leading dim of transposed feature matrix
#define MB 64      // goals per block
#define NB 128     // features per tile
#define NSPLIT 4   // feature-dim split per step
#define NPTS 8192

// ---------------- scratch (__device__ globals; no allocation) ----------------
__device__ float g_FT[KD * LD];          // transposed features [64][8192]
__device__ float g_norms[LD];            // |f|^2
__device__ unsigned g_candU[4096 * NSPLIT * 3];
__device__ int      g_candI[4096 * NSPLIT * 3];
__device__ ull g_kA[NPTS], g_kB[NPTS];   // round-1/2 sort keys (bits<<32|pos)
__device__ int g_rA[NPTS], g_rB[NPTS];   // ranks
__device__ int g_perm[NPTS];             // final permutation (rand_inds = first 4096)

// ---------------- threefry2x32 (exact JAX) ----------------
__device__ __forceinline__ void tf2x32(unsigned k0, unsigned k1,
                                       unsigned c0, unsigned c1,
                                       unsigned &o0, unsigned &o1) {
    unsigned ks2 = k0 ^ k1 ^ 0x1BD11BDAu;
    unsigned x0 = c0 + k0, x1 = c1 + k1;
#define TF_RND(r) { x0 += x1; x1 = (x1 << (r)) | (x1 >> (32 - (r))); x1 ^= x0; }
    TF_RND(13) TF_RND(15) TF_RND(26) TF_RND(6)   x0 += k1;  x1 += ks2 + 1u;
    TF_RND(17) TF_RND(29) TF_RND(16) TF_RND(24)  x0 += ks2; x1 += k0 + 2u;
    TF_RND(13) TF_RND(15) TF_RND(26) TF_RND(6)   x0 += k0;  x1 += k1 + 3u;
    TF_RND(17) TF_RND(29) TF_RND(16) TF_RND(24)  x0 += k1;  x1 += ks2 + 4u;
    TF_RND(13) TF_RND(15) TF_RND(26) TF_RND(6)   x0 += ks2; x1 += k0 + 5u;
#undef TF_RND
    o0 = x0; o1 = x1;
}

// partitionable threefry: round r: key,subkey = split(key), counters (0,0),(0,1)
__device__ __forceinline__ void subkeys(unsigned &s10, unsigned &s11,
                                        unsigned &s20, unsigned &s21) {
    unsigned n0, n1;
    tf2x32(0u, 42u, 0u, 0u, n0, n1);
    tf2x32(0u, 42u, 0u, 1u, s10, s11);
    tf2x32(n0, n1, 0u, 1u, s20, s21);
}

// bits[i] = y0 ^ y1 with counter (0, i); stable-sort key = (bits<<32) | i.
// Also zeroes the rank arrays (graph replays must be deterministic).
__global__ void keys_k() {
    int i = blockIdx.x * blockDim.x + threadIdx.x;
    if (i >= NPTS) return;
    unsigned s10, s11, s20, s21;
    subkeys(s10, s11, s20, s21);
    unsigned lo, hi;
    tf2x32(s10, s11, 0u, (unsigned)i, lo, hi);
    g_kA[i] = ((ull)(lo ^ hi) << 32) | (unsigned)i;
    tf2x32(s20, s21, 0u, (unsigned)i, lo, hi);
    g_kB[i] = ((ull)(lo ^ hi) << 32) | (unsigned)i;
    g_rA[i] = 0; g_rB[i] = 0;
}

// rank[i] = #{j : key_j < key_i}, segmented 4-way over j, REDG-accumulated.
#define SEG 2048
__global__ __launch_bounds__(256) void rank_k() {
    __shared__ ull tile[SEG];
    const ull* K = blockIdx.y ? g_kB : g_kA;
    int* R = blockIdx.y ? g_rB : g_rA;
    int i = blockIdx.x * 256 + threadIdx.x;
    int base = blockIdx.z * SEG;
    ull my = K[i];
    for (int j = threadIdx.x; j < SEG; j += 256) tile[j] = K[base + j];
    __syncthreads();
    int cnt = 0;
#pragma unroll 8
    for (int j = 0; j < SEG; j++) cnt += (tile[j] < my);
    atomicAdd(&R[i], cnt);
}

// perm[rB[rA[i]]] = i
__global__ void compose_k() {
    int i = blockIdx.x * blockDim.x + threadIdx.x;
    if (i >= NPTS) return;
    g_perm[g_rB[g_rA[i]]] = i;
}

// ---------------- transpose rows[n][64] -> g_FT[64][foff+...] ----------------
__global__ void transpose_k(const float* __restrict__ in, int foff) {
    __shared__ float t[32][33];
    int f0 = blockIdx.x * 32, d0 = blockIdx.y * 32;
    int tx = threadIdx.x, ty = threadIdx.y;
    t[ty][tx] = in[(size_t)(f0 + ty) * KD + d0 + tx];
    __syncthreads();
    g_FT[(size_t)(d0 + ty) * LD + foff + f0 + tx] = t[tx][ty];
}

// ---------------- norms: |f|^2 for f in [foff, foff+n) ----------------
__global__ void norms_k(int foff) {
    int f = foff + blockIdx.x * blockDim.x + threadIdx.x;
    float s = 0.f;
#pragma unroll
    for (int k = 0; k < KD; k++) {
        float v = g_FT[(size_t)k * LD + f];
        s = __fadd_rn(s, __fmul_rn(v, v));
    }
    g_norms[f] = s;
}

// ---------------- ordered-float key for tie-break-by-lower-index min ----------------
__device__ __forceinline__ unsigned fkey(float f) {
    unsigned u = __float_as_uint(f);
    return (u & 0x80000000u) ? ~u : (u | 0x80000000u);
}

__device__ __forceinline__ void fma_x2(ull &acc, ull a, ull b) {
    asm("fma.rn.f32x2 %0, %1, %2, %3;" : "=l"(acc) : "l"(a), "l"(b), "l"(acc));
}

__device__ __forceinline__ void top3_ins(float v, int idx, float* bv, int* bi) {
    if (v < bv[2]) {
        if (v < bv[1]) {
            bv[2] = bv[1]; bi[2] = bi[1];
            if (v < bv[0]) {
                bv[1] = bv[0]; bi[1] = bi[0];
                bv[0] = v; bi[0] = idx;
            } else { bv[1] = v; bi[1] = idx; }
        } else { bv[2] = v; bi[2] = idx; }
    }
}

// ---------------- KNN top-3: f32x2 GEMM-tiled, crossbar/fma balanced ----------------
// grid = (4096/MB, NSPLIT), block = 256 (8 warps). Warp w owns goals [w*8, w*8+8);
// lane owns feats lane*4..+3 of the 128-feat tile. Goals pair-duplicated in smem:
// row k = [g0,g0,g1,g1,...]; one LDS.128 broadcast feeds 2 goals (2 f32x2 splats).
// Per warp-k: 1 LDS.128 (4 wf) + 4 LDS.128bc (4 wf) + 16 FFMA2 -> both pipes @128/k.
__global__ __launch_bounds__(256, 2) void knn_k(int nfeat, int usePerm) {
    extern __shared__ float sm[];
    float* Fs = sm;                        // [64][128]   feats
    float* Gp = Fs + KD * NB;              // [64][64*2]  pair-duplicated goals
    float* Ns = Gp + KD * MB * 2;          // [128]
    float* Gn = Ns + NB;                   // [64]
    ulonglong2* FsV = (ulonglong2*)Fs;     // row k: 32 entries (16B = 4 feats)
    float4* Gp4 = (float4*)Gp;             // row k: 32 entries ({g,g,g',g'})
    float4* Ns4 = (float4*)Ns;

    int tid = threadIdx.x;
    int lane = tid & 31, w = tid >> 5;
    int g0 = blockIdx.x * MB;
    int part = nfeat / NSPLIT;
    int fBeg = blockIdx.y * part, fEnd = fBeg + part;

    for (int i = tid; i < KD * MB; i += 256) {
        int k = i >> 6, j = i & 63;
        int src = usePerm ? g_perm[g0 + j] : (g0 + j);
        float v = g_FT[(size_t)k * LD + src];
        ((float2*)Gp)[k * MB + j] = make_float2(v, v);
    }
    if (tid < MB) {
        int src = usePerm ? g_perm[g0 + tid] : (g0 + tid);
        Gn[tid] = g_norms[src];
    }

    float bv[8][3]; int bi[8][3];
#pragma unroll
    for (int r = 0; r < 8; r++)
#pragma unroll
        for (int t = 0; t < 3; t++) { bv[r][t] = 3.402823466e38f; bi[r][t] = 0; }

    for (int f0 = fBeg; f0 < fEnd; f0 += NB) {
        __syncthreads();
        for (int i = tid; i < KD * NB / 4; i += 256) {
            int k = i >> 5, c = i & 31;
            ((float4*)Fs)[k * 32 + c] =
                *reinterpret_cast<const float4*>(&g_FT[(size_t)k * LD + f0 + 4 * c]);
        }
        if (tid < NB) Ns[tid] = g_norms[f0 + tid];
        __syncthreads();

        ull acc[8][2];
#pragma unroll
        for (int r = 0; r < 8; r++) { acc[r][0] = 0ull; acc[r][1] = 0ull; }

#pragma unroll 16
        for (int k = 0; k < KD; k++) {
            ulonglong2 fq = FsV[k * 32 + lane];   // feats lane*4 .. +3
#pragma unroll
            for (int i = 0; i < 4; i++) {
                float4 gq = Gp4[k * 32 + w * 4 + i];     // {g2i, g2i, g2i+1, g2i+1}
                ull u0 = ((ulonglong2*)&gq)->x;
                ull u1 = ((ulonglong2*)&gq)->y;
                fma_x2(acc[2*i+0][0], u0, fq.x);
                fma_x2(acc[2*i+0][1], u0, fq.y);
                fma_x2(acc[2*i+1][0], u1, fq.x);
                fma_x2(acc[2*i+1][1], u1, fq.y);
            }
        }

        float4 nf4 = Ns4[lane];
        float nf[4] = { nf4.x, nf4.y, nf4.z, nf4.w };
        int base = f0 + lane * 4;
#pragma unroll
        for (int r = 0; r < 8; r++) {
            float gn = Gn[w * 8 + r];
#pragma unroll
            for (int p = 0; p < 2; p++) {
                float dlo = __uint_as_float((unsigned)(acc[r][p]));
                float dhi = __uint_as_float((unsigned)(acc[r][p] >> 32));
                float v0 = fmaf(-2.0f, dlo, gn + nf[p * 2]);
                float v1 = fmaf(-2.0f, dhi, gn + nf[p * 2 + 1]);
                top3_ins(v0, base + p * 2,     bv[r], bi[r]);
                top3_ins(v1, base + p * 2 + 1, bv[r], bi[r]);
            }
        }
    }

    // per-goal warp merge: 3 rounds of u64 min + pop (keys unique: idx unique)
#pragma unroll
    for (int r = 0; r < 8; r++) {
        ull cand[3];
#pragma unroll
        for (int t = 0; t < 3; t++)
            cand[t] = ((ull)fkey(bv[r][t]) << 32) | (unsigned)bi[r][t];
        int p = 0;
#pragma unroll
        for (int t = 0; t < 3; t++) {
            ull cur = (p < 3) ? cand[p] : ~0ull;
            ull m = cur;
            for (int off = 16; off; off >>= 1) {
                ull o = __shfl_xor_sync(0xffffffffu, m, off);
                if (o < m) m = o;
            }
            if (cur == m) p++;
            if (lane == 0) {
                int g = g0 + w * 8 + r;
                int base2 = (g * NSPLIT + blockIdx.y) * 3 + t;
                g_candU[base2] = (unsigned)(m >> 32);
                g_candI[base2] = (int)(m & 0xffffffffu);
            }
        }
    }
}

// ---------------- merge split candidates + gather mean ----------------
__global__ void finalize_k(const float* __restrict__ Frow, int ngoals,
                           float* __restrict__ outp) {
    int w = threadIdx.x >> 5, lane = threadIdx.x & 31;
    int g = blockIdx.x * 8 + w;
    if (g >= ngoals) return;
    ull key = ~0ull;
    if (lane < NSPLIT * 3)
        key = ((ull)g_candU[g * NSPLIT * 3 + lane] << 32) |
              (unsigned)g_candI[g * NSPLIT * 3 + lane];
    int idxs[3];
#pragma unroll
    for (int t = 0; t < 3; t++) {
        ull m = key;
        for (int off = 16; off; off >>= 1) {
            ull o = __shfl_xor_sync(0xffffffffu, m, off);
            if (o < m) m = o;
        }
        if (key == m) key = ~0ull;
        idxs[t] = (int)(m & 0xffffffffu);
    }
    const float* r0 = Frow + (size_t)idxs[0] * KD;
    const float* r1 = Frow + (size_t)idxs[1] * KD;
    const float* r2 = Frow + (size_t)idxs[2] * KD;
#pragma unroll
    for (int d = lane; d < KD; d += 32)
        outp[(size_t)g * KD + d] = ((r0[d] + r1[d]) + r2[d]) / 3.0f;
}

// ---------------- orchestration ----------------
extern "C" void kernel_launch(void* const* d_in, const int* in_sizes, int n_in,
                              void* d_out, int out_size) {
    const float* x = (const float*)d_in[0];   // [4096, 64] fp32
    float* out = (float*)d_out;               // [12288, 64] fp32

    const int KNN_SMEM = KD * NB * 4 + KD * MB * 8 + NB * 4 + MB * 4;  // 66304
    cudaFuncSetAttribute(knn_k, cudaFuncAttributeMaxDynamicSharedMemorySize,
                         KNN_SMEM);

    // permutation via segmented rank counting (needed only for step 2)
    keys_k<<<NPTS / 512, 512>>>();
    rank_k<<<dim3(NPTS / 256, 2, NPTS / SEG), 256>>>();
    compose_k<<<NPTS / 512, 512>>>();

    // rows [0, 4096) = x
    cudaMemcpyAsync(out, x, (size_t)4096 * KD * sizeof(float),
                    cudaMemcpyDeviceToDevice);

    // ---- step 1: feats = goals = x (4096) ----
    transpose_k<<<dim3(4096 / 32, 2), dim3(32, 32)>>>(x, 0);
    norms_k<<<4096 / 256, 256>>>(0);
    knn_k<<<dim3(4096 / MB, NSPLIT), 256, KNN_SMEM>>>(4096, 0);
    finalize_k<<<4096 / 8, 256>>>(x, 4096, out + (size_t)4096 * KD);

    // ---- step 2: feats = out[0:8192], goals = feats[perm[:4096]] ----
    // columns [0,4096) of g_FT and their norms are unchanged; add only the new rows
    transpose_k<<<dim3(4096 / 32, 2), dim3(32, 32)>>>(out + (size_t)4096 * KD, 4096);
    norms_k<<<4096 / 256, 256>>>(4096);
    knn_k<<<dim3(4096 / MB, NSPLIT), 256, KNN_SMEM>>>(8192, 1);
    finalize_k<<<4096 / 8, 256>>>(out, 4096, out + (size_t)8192 * KD);
}